// round 7
// baseline (speedup 1.0000x reference)
#include <cuda_runtime.h>
#include <math.h>
#include <stdint.h>

#define NN     50000
#define NE     800000
#define EF     16
#define HID    64
#define NC     10
#define NPICK  4096
#define NSCB   196            // ceil(NN/256)
#define EBLK   25000          // NE / 32

typedef unsigned long long ull;

// ---------------- scratch (static device globals; no allocation) ----------------
__device__ float  g_M[EF * 256];         // folded gate weights, [k][l*64+j]
__device__ float  g_c[256];              // folded gate bias, [l*64+j]
__device__ float4 g_gate[NE];            // 4 per-layer gates, edge-id order
__device__ float  g_deg[4 * NN];         // per-layer degree sums (atomic)
__device__ __align__(256) float g_h[NN * HID];    // h' = dis * (x @ W)
__device__ __align__(256) float g_xa[NN * HID];
__device__ __align__(256) float g_xb[NN * HID];
__device__ int    g_cnt[NN];
__device__ int    g_tmp[NN];
__device__ int    g_bsum[256];
__device__ int    g_boff[256];
__device__ int    g_rowptr[NN + 1];
__device__ int    g_pos[NN];
__device__ int2   g_se[NE];              // CSR: (src node, edge id) per slot

__device__ __forceinline__ int clampi(int v, int hi) {
    return v < 0 ? 0 : (v >= hi ? hi - 1 : v);
}
__device__ __forceinline__ ull pack2(float x) {
    ull r; unsigned int b = __float_as_uint(x);
    asm("mov.b64 %0, {%1, %2};" : "=l"(r) : "r"(b), "r"(b));
    return r;
}
__device__ __forceinline__ void fma2(ull& d, ull a, ull b) {
    asm("fma.rn.f32x2 %0, %1, %2, %0;" : "+l"(d) : "l"(a), "l"(b));
}
__device__ __forceinline__ void unpack2(ull v, float& lo, float& hi) {
    unsigned int l, h;
    asm("mov.b64 {%0, %1}, %2;" : "=r"(l), "=r"(h) : "l"(v));
    lo = __uint_as_float(l); hi = __uint_as_float(h);
}

// ---------------- weight folding: M = (encW1@encW2)@mlpW1, [k][l*64+j] layout ----------------
__global__ __launch_bounds__(256) void k_fold(
    const float* __restrict__ encW1, const float* __restrict__ encb1,
    const float* __restrict__ encW2, const float* __restrict__ encb2,
    const float* __restrict__ mlpW1, const float* __restrict__ mlpb1)
{
    __shared__ float sW1[256], sW2[256], sWc[256], sbc[16];
    int tid = threadIdx.x;
    sW1[tid] = encW1[tid];
    sW2[tid] = encW2[tid];
    __syncthreads();
    {   // Wc = W1 @ W2 (16x16)
        int i = tid >> 4, j = tid & 15;
        float s = 0.f;
        #pragma unroll
        for (int k = 0; k < EF; k++) s += sW1[i * EF + k] * sW2[k * EF + j];
        sWc[tid] = s;
    }
    if (tid < EF) {
        float s = encb2[tid];
        #pragma unroll
        for (int k = 0; k < EF; k++) s += encb1[k] * sW2[k * EF + tid];
        sbc[tid] = s;
    }
    __syncthreads();
    #pragma unroll 1
    for (int m = 0; m < 16; m++) {
        int idx = tid + 256 * m;                 // 0..4095
        int l = idx >> 10, k = (idx >> 6) & 15, j = idx & 63;
        float s = 0.f;
        #pragma unroll
        for (int i = 0; i < EF; i++) s += sWc[k * EF + i] * mlpW1[(l * EF + i) * HID + j];
        g_M[k * 256 + l * 64 + j] = s;           // [k][n] layout, n = l*64+j
    }
    {
        int l = tid >> 6, j = tid & 63;
        float s = mlpb1[l * HID + j];
        #pragma unroll
        for (int i = 0; i < EF; i++) s += sbc[i] * mlpW1[(l * EF + i) * HID + j];
        g_c[tid] = s;                            // n = tid = l*64+j
    }
}

// ---------------- zero counters ----------------
__global__ void k_zero() {
    int i = blockIdx.x * blockDim.x + threadIdx.x;
    if (i < 4 * NN) g_deg[i] = 0.f;
    if (i < NN) g_cnt[i] = 0;
}

// ---------------- CSR build ----------------
__global__ void k_count(const int* __restrict__ colp) {
    int e = blockIdx.x * blockDim.x + threadIdx.x;
    if (e < NE) atomicAdd(&g_cnt[clampi(colp[e], NN)], 1);
}

// ---------------- tiled edge-gate GEMM: 32 edges x 256 outputs per block ----------------
// thread tile: 4 edges x 8 outputs (4 f32x2 pairs). eg = tid>>5, ng = tid&31, n0 = 8*ng
__global__ __launch_bounds__(256) void k_edge(const float* __restrict__ eattr,
                                              const int* __restrict__ colp,
                                              const float* __restrict__ mlpW2,
                                              const float* __restrict__ mlpb2)
{
    __shared__ __align__(16) float sA[EF][32];     // a-tile transposed: [k][edge]
    __shared__ __align__(16) float sW[EF][256];    // folded M: [k][n]
    __shared__ __align__(16) float sC[256];        // folded bias [n]
    __shared__ __align__(16) float sV[256];        // mlpW2 flattened [n]
    __shared__ float sB[4];

    int tid = threadIdx.x;
    {   // weights: 16 KB straight copy
        const float4* src = (const float4*)g_M;
        float4* dst = (float4*)&sW[0][0];
        #pragma unroll
        for (int i = 0; i < 4; i++) dst[tid + 256 * i] = src[tid + 256 * i];
    }
    sC[tid] = g_c[tid];
    sV[tid] = mlpW2[tid];
    if (tid < 4) sB[tid] = mlpb2[tid];
    if (tid < 128) {   // a-tile: 32 rows x 16 floats, transposed
        int row = tid >> 2, q = tid & 3;
        float4 v = ((const float4*)(eattr + ((size_t)blockIdx.x * 32 + row) * EF))[q];
        sA[q * 4 + 0][row] = v.x;
        sA[q * 4 + 1][row] = v.y;
        sA[q * 4 + 2][row] = v.z;
        sA[q * 4 + 3][row] = v.w;
    }
    __syncthreads();

    const int eg = tid >> 5;        // edges 4*eg .. 4*eg+3
    const int ng = tid & 31;        // outputs n0 .. n0+7
    const int n0 = ng * 8;

    ull acc[4][4];
    {
        ulonglong2 c01 = *(const ulonglong2*)&sC[n0];
        ulonglong2 c23 = *(const ulonglong2*)&sC[n0 + 4];
        #pragma unroll
        for (int e = 0; e < 4; e++) {
            acc[e][0] = c01.x; acc[e][1] = c01.y;
            acc[e][2] = c23.x; acc[e][3] = c23.y;
        }
    }

    #pragma unroll
    for (int k = 0; k < EF; k++) {
        ulonglong2 wA = *(const ulonglong2*)&sW[k][n0];      // LDS.128, no repack
        ulonglong2 wB = *(const ulonglong2*)&sW[k][n0 + 4];
        float4 a4 = *(const float4*)&sA[k][eg * 4];          // LDS.128 broadcast
        float av[4] = {a4.x, a4.y, a4.z, a4.w};
        #pragma unroll
        for (int e = 0; e < 4; e++) {
            ull ae = pack2(av[e]);
            fma2(acc[e][0], ae, wA.x);
            fma2(acc[e][1], ae, wA.y);
            fma2(acc[e][2], ae, wB.x);
            fma2(acc[e][3], ae, wB.y);
        }
    }

    // epilogue: partial z = sum relu(h)*w2 over this thread's 8 outputs
    float w2v[8];
    #pragma unroll
    for (int i = 0; i < 8; i++) w2v[i] = sV[n0 + i];
    float pz[4];
    #pragma unroll
    for (int e = 0; e < 4; e++) {
        float s = 0.f;
        #pragma unroll
        for (int np = 0; np < 4; np++) {
            float lo, hi; unpack2(acc[e][np], lo, hi);
            s += fmaxf(lo, 0.f) * w2v[2 * np] + fmaxf(hi, 0.f) * w2v[2 * np + 1];
        }
        pz[e] = s;
    }
    #pragma unroll
    for (int off = 1; off < 8; off <<= 1) {
        #pragma unroll
        for (int e = 0; e < 4; e++)
            pz[e] += __shfl_xor_sync(0xffffffffu, pz[e], off);
    }
    if ((ng & 7) == 0) {
        int l = ng >> 3;
        float bl = sB[l];
        #pragma unroll
        for (int e = 0; e < 4; e++) {
            int eglob = blockIdx.x * 32 + eg * 4 + e;
            float z = pz[e] + bl;
            float g = 1.f / (1.f + __expf(-z));
            ((float*)&g_gate[eglob])[l] = g;                 // edge-id order
            atomicAdd(&g_deg[l * NN + clampi(colp[eglob], NN)], g);
        }
    }
}

__global__ void k_scan1() {
    __shared__ int sh[256];
    int tid = threadIdx.x;
    int i = blockIdx.x * 256 + tid;
    int v = (i < NN) ? g_cnt[i] : 0;
    sh[tid] = v; __syncthreads();
    #pragma unroll
    for (int off = 1; off < 256; off <<= 1) {
        int t = (tid >= off) ? sh[tid - off] : 0;
        __syncthreads();
        sh[tid] += t;
        __syncthreads();
    }
    if (i < NN) g_tmp[i] = sh[tid] - v;
    if (tid == 255) g_bsum[blockIdx.x] = sh[255];
}

__global__ void k_scan2() {
    __shared__ int sh[256];
    int tid = threadIdx.x;
    int v = (tid < NSCB) ? g_bsum[tid] : 0;
    sh[tid] = v; __syncthreads();
    #pragma unroll
    for (int off = 1; off < 256; off <<= 1) {
        int t = (tid >= off) ? sh[tid - off] : 0;
        __syncthreads();
        sh[tid] += t;
        __syncthreads();
    }
    g_boff[tid] = sh[tid] - v;
}

__global__ void k_scan3() {
    int i = blockIdx.x * 256 + threadIdx.x;
    if (i < NN) {
        int r = g_tmp[i] + g_boff[blockIdx.x];
        g_rowptr[i] = r;
        g_pos[i] = r;
    }
    if (i == 0) g_rowptr[NN] = NE;
}

__global__ void k_scatter(const int* __restrict__ rowp,
                          const int* __restrict__ colp) {
    int e = blockIdx.x * blockDim.x + threadIdx.x;
    if (e >= NE) return;
    int c = clampi(colp[e], NN);
    int p = atomicAdd(&g_pos[c], 1);
    p = clampi(p, NE);
    g_se[p] = make_int2(clampi(rowp[e], NN), e);
}

// ---------------- h' = rsqrt(deg+1) * (x @ W), warp per row, f32x2 ----------------
__global__ __launch_bounds__(256) void k_gemm(const float* __restrict__ xin,
                                              const float* __restrict__ W,
                                              const float* __restrict__ degl) {
    __shared__ __align__(16) float sWf[HID * HID];
    for (int i = threadIdx.x; i < HID * HID; i += 256) sWf[i] = W[i];
    __syncthreads();
    int w = (blockIdx.x * 256 + threadIdx.x) >> 5;
    int lane = threadIdx.x & 31;
    if (w >= NN) return;
    float2 xv = *(const float2*)&xin[(size_t)w * HID + lane * 2];
    const ull* sW = (const ull*)sWf;
    ull acc = 0;
    #pragma unroll
    for (int k = 0; k < HID; k++) {
        float xk = __shfl_sync(0xffffffffu, (k & 1) ? xv.y : xv.x, k >> 1);
        fma2(acc, pack2(xk), sW[k * 32 + lane]);
    }
    float d = rsqrtf(degl[w] + 1.f);
    float lo, hi; unpack2(acc, lo, hi);
    *(float2*)&g_h[(size_t)w * HID + lane * 2] = make_float2(lo * d, hi * d);
}

// ---------------- SpMM: out[c] = disc*(sum ew*h'[src] + h'[c]) + b ----------------
__global__ __launch_bounds__(256) void k_spmm(const float* __restrict__ degl,
                                              const float* __restrict__ bias,
                                              float* __restrict__ xout,
                                              int l, int dorelu) {
    int c = (blockIdx.x * blockDim.x + threadIdx.x) >> 5;
    int lane = threadIdx.x & 31;
    if (c >= NN) return;
    int rs = g_rowptr[c], re = g_rowptr[c + 1];
    ull acc = 0;
    #pragma unroll 4
    for (int p = rs; p < re; p++) {
        int2 se = g_se[p];
        float ew = ((const float*)&g_gate[se.y])[l];
        ull hvp = *(const ull*)&g_h[(size_t)se.x * HID + lane * 2];
        fma2(acc, pack2(ew), hvp);
    }
    {   // self loop: + h'[c]
        ull hvp = *(const ull*)&g_h[(size_t)c * HID + lane * 2];
        fma2(acc, pack2(1.f), hvp);
    }
    float disc = rsqrtf(degl[c] + 1.f);
    float lo, hi; unpack2(acc, lo, hi);
    float2 b = *(const float2*)&bias[lane * 2];
    lo = lo * disc + b.x; hi = hi * disc + b.y;
    if (dorelu) { lo = fmaxf(lo, 0.f); hi = fmaxf(hi, 0.f); }
    *(float2*)&xout[(size_t)c * HID + lane * 2] = make_float2(lo, hi);
}

// ---------------- classifier + softmax at picked nodes ----------------
__global__ __launch_bounds__(128) void k_final(const float* __restrict__ xin,
                                               const float* __restrict__ linW,
                                               const float* __restrict__ linb,
                                               const int* __restrict__ pick,
                                               float* __restrict__ out) {
    __shared__ float sW[HID * NC];
    __shared__ float sb[NC];
    for (int i = threadIdx.x; i < HID * NC; i += 128) sW[i] = linW[i];
    if (threadIdx.x < NC) sb[threadIdx.x] = linb[threadIdx.x];
    __syncthreads();
    int t = blockIdx.x * 128 + threadIdx.x;
    if (t >= NPICK) return;
    int node = clampi(pick[t], NN);
    float lg[NC];
    #pragma unroll
    for (int j = 0; j < NC; j++) lg[j] = sb[j];
    const float4* xr = (const float4*)&xin[(size_t)node * HID];
    #pragma unroll
    for (int k4 = 0; k4 < 16; k4++) {
        float4 v = xr[k4];
        float xs[4] = {v.x, v.y, v.z, v.w};
        #pragma unroll
        for (int q = 0; q < 4; q++) {
            #pragma unroll
            for (int j = 0; j < NC; j++) lg[j] += xs[q] * sW[(k4 * 4 + q) * NC + j];
        }
    }
    float m = lg[0];
    #pragma unroll
    for (int j = 1; j < NC; j++) m = fmaxf(m, lg[j]);
    float ex[NC], s = 0.f;
    #pragma unroll
    for (int j = 0; j < NC; j++) { ex[j] = __expf(lg[j] - m); s += ex[j]; }
    float inv = 1.f / s;
    #pragma unroll
    for (int j = 0; j < NC; j++) out[(size_t)t * NC + j] = ex[j] * inv;
}

// ---------------- launch ----------------
extern "C" void kernel_launch(void* const* d_in, const int* in_sizes, int n_in,
                              void* d_out, int out_size) {
    const float* x      = (const float*)d_in[0];
    const float* eattr  = (const float*)d_in[1];
    const float* encW1  = (const float*)d_in[2];
    const float* encb1  = (const float*)d_in[3];
    const float* encW2  = (const float*)d_in[4];
    const float* encb2  = (const float*)d_in[5];
    const float* convW  = (const float*)d_in[6];
    const float* convB  = (const float*)d_in[7];
    const float* mlpW1  = (const float*)d_in[8];
    const float* mlpb1  = (const float*)d_in[9];
    const float* mlpW2  = (const float*)d_in[10];
    const float* mlpb2  = (const float*)d_in[11];
    const float* linW   = (const float*)d_in[12];
    const float* linb   = (const float*)d_in[13];
    const int* eidx     = (const int*)d_in[14];   // int32 (JAX x64 disabled)
    const int* pick     = (const int*)d_in[15];
    float* out = (float*)d_out;

    const int* rowp = eidx;
    const int* colp = eidx + NE;

    float *xa, *xb, *deg;
    cudaGetSymbolAddress((void**)&xa, g_xa);
    cudaGetSymbolAddress((void**)&xb, g_xb);
    cudaGetSymbolAddress((void**)&deg, g_deg);

    const int EB = (NE + 255) / 256;        // 3125
    const int WB = (NN * 32 + 255) / 256;   // 6250

    // launch index 0..2
    k_fold<<<1, 256>>>(encW1, encb1, encW2, encb2, mlpW1, mlpb1);
    k_zero<<<(4 * NN + 255) / 256, 256>>>();
    k_count<<<EB, 256>>>(colp);

    // launch index 3: k_edge (lands in the ncu -s window)
    k_edge<<<EBLK, 256>>>(eattr, colp, mlpW2, mlpb2);

    // CSR scan + scatter
    k_scan1<<<NSCB, 256>>>();
    k_scan2<<<1, 256>>>();
    k_scan3<<<NSCB, 256>>>();
    k_scatter<<<EB, 256>>>(rowp, colp);

    const float* xin = x;
    float* bufs[2] = { xa, xb };
    for (int l = 0; l < 4; l++) {
        k_gemm<<<WB, 256>>>(xin, convW + l * HID * HID, deg + l * NN);
        k_spmm<<<WB, 256>>>(deg + l * NN, convB + l * HID, bufs[l & 1], l, (l < 3) ? 1 : 0);
        xin = bufs[l & 1];
    }

    k_final<<<32, 128>>>(xin, linW, linb, pick, out);
}

// round 8
// speedup vs baseline: 1.1410x; 1.1410x over previous
#include <cuda_runtime.h>
#include <math.h>
#include <stdint.h>

#define NN     50000
#define NE     800000
#define EF     16
#define HID    64
#define NC     10
#define NPICK  4096
#define NSCB   196            // ceil(NN/256)
#define EBLK   12500          // NE / 64

typedef unsigned long long ull;

// ---------------- scratch (static device globals; no allocation) ----------------
__device__ float  g_M[EF * 256];         // folded gate weights, [k][l*64+j]
__device__ float  g_c[256];              // folded gate bias, [l*64+j]
__device__ float4 g_gate[NE];            // 4 per-layer gates, edge-id order
__device__ float  g_deg[4 * NN];         // per-layer degree sums (atomic)
__device__ __align__(256) float g_h[NN * HID];    // h' = dis * (x @ W)
__device__ __align__(256) float g_xa[NN * HID];
__device__ __align__(256) float g_xb[NN * HID];
__device__ int    g_cnt[NN];
__device__ int    g_tmp[NN];
__device__ int    g_bsum[256];
__device__ int    g_boff[256];
__device__ int    g_rowptr[NN + 1];
__device__ int    g_pos[NN];
__device__ int2   g_se[NE];              // CSR: (src node, edge id) per slot

__device__ __forceinline__ int clampi(int v, int hi) {
    return v < 0 ? 0 : (v >= hi ? hi - 1 : v);
}
__device__ __forceinline__ ull pack2(float x) {
    ull r; unsigned int b = __float_as_uint(x);
    asm("mov.b64 %0, {%1, %2};" : "=l"(r) : "r"(b), "r"(b));
    return r;
}
__device__ __forceinline__ void fma2(ull& d, ull a, ull b) {
    asm("fma.rn.f32x2 %0, %1, %2, %0;" : "+l"(d) : "l"(a), "l"(b));
}
__device__ __forceinline__ void unpack2(ull v, float& lo, float& hi) {
    unsigned int l, h;
    asm("mov.b64 {%0, %1}, %2;" : "=r"(l), "=r"(h) : "l"(v));
    lo = __uint_as_float(l); hi = __uint_as_float(h);
}

// ---------------- weight folding: M = (encW1@encW2)@mlpW1, [k][l*64+j] layout ----------------
__global__ __launch_bounds__(256) void k_fold(
    const float* __restrict__ encW1, const float* __restrict__ encb1,
    const float* __restrict__ encW2, const float* __restrict__ encb2,
    const float* __restrict__ mlpW1, const float* __restrict__ mlpb1)
{
    __shared__ float sW1[256], sW2[256], sWc[256], sbc[16];
    int tid = threadIdx.x;
    sW1[tid] = encW1[tid];
    sW2[tid] = encW2[tid];
    __syncthreads();
    {   // Wc = W1 @ W2 (16x16)
        int i = tid >> 4, j = tid & 15;
        float s = 0.f;
        #pragma unroll
        for (int k = 0; k < EF; k++) s += sW1[i * EF + k] * sW2[k * EF + j];
        sWc[tid] = s;
    }
    if (tid < EF) {
        float s = encb2[tid];
        #pragma unroll
        for (int k = 0; k < EF; k++) s += encb1[k] * sW2[k * EF + tid];
        sbc[tid] = s;
    }
    __syncthreads();
    #pragma unroll 1
    for (int m = 0; m < 16; m++) {
        int idx = tid + 256 * m;                 // 0..4095
        int l = idx >> 10, k = (idx >> 6) & 15, j = idx & 63;
        float s = 0.f;
        #pragma unroll
        for (int i = 0; i < EF; i++) s += sWc[k * EF + i] * mlpW1[(l * EF + i) * HID + j];
        g_M[k * 256 + l * 64 + j] = s;           // [k][n] layout, n = l*64+j
    }
    {
        int l = tid >> 6, j = tid & 63;
        float s = mlpb1[l * HID + j];
        #pragma unroll
        for (int i = 0; i < EF; i++) s += sbc[i] * mlpW1[(l * EF + i) * HID + j];
        g_c[tid] = s;                            // n = tid = l*64+j
    }
}

// ---------------- zero counters ----------------
__global__ void k_zero() {
    int i = blockIdx.x * blockDim.x + threadIdx.x;
    if (i < 4 * NN) g_deg[i] = 0.f;
    if (i < NN) g_cnt[i] = 0;
}

// ---------------- CSR build ----------------
__global__ void k_count(const int* __restrict__ colp) {
    int e = blockIdx.x * blockDim.x + threadIdx.x;
    if (e < NE) atomicAdd(&g_cnt[clampi(colp[e], NN)], 1);
}

// ---------------- tiled edge-gate GEMM: 64 edges x 256 outputs per block ----------------
// warp tile: 8 edges x 256 outputs. thread tile: 8 edges x (4+4) outputs:
// chunk A = [4*ng, 4*ng+4)  (layers 0/1), chunk B = [128+4*ng, ...) (layers 2/3).
// All weight LDS.128 are lane-contiguous -> conflict-free.
__global__ __launch_bounds__(256, 2) void k_edge(const float* __restrict__ eattr,
                                                 const int* __restrict__ colp,
                                                 const float* __restrict__ mlpW2,
                                                 const float* __restrict__ mlpb2)
{
    __shared__ __align__(16) float sA[EF][64];     // a-tile transposed: [k][edge]
    __shared__ __align__(16) float sW[EF][256];    // folded M: [k][n]
    __shared__ __align__(16) float sC[256];        // folded bias [n]
    __shared__ __align__(16) float sV[256];        // mlpW2 flattened [n]
    __shared__ float sB[4];

    int tid = threadIdx.x;
    {   // weights: 16 KB straight copy
        const float4* src = (const float4*)g_M;
        float4* dst = (float4*)&sW[0][0];
        #pragma unroll
        for (int i = 0; i < 4; i++) dst[tid + 256 * i] = src[tid + 256 * i];
    }
    sC[tid] = g_c[tid];
    sV[tid] = mlpW2[tid];
    if (tid < 4) sB[tid] = mlpb2[tid];
    {   // a-tile: 64 rows x 16 floats, transposed
        int row = tid >> 2, q = tid & 3;
        float4 v = ((const float4*)(eattr + ((size_t)blockIdx.x * 64 + row) * EF))[q];
        sA[q * 4 + 0][row] = v.x;
        sA[q * 4 + 1][row] = v.y;
        sA[q * 4 + 2][row] = v.z;
        sA[q * 4 + 3][row] = v.w;
    }
    __syncthreads();

    const int eg = tid >> 5;        // warp -> edges 8*eg .. 8*eg+7
    const int ng = tid & 31;
    const int nA = 4 * ng;          // chunk A
    const int nB = 128 + 4 * ng;    // chunk B

    ull accA[8][2], accB[8][2];
    {
        ulonglong2 cA = *(const ulonglong2*)&sC[nA];
        ulonglong2 cB = *(const ulonglong2*)&sC[nB];
        #pragma unroll
        for (int e = 0; e < 8; e++) {
            accA[e][0] = cA.x; accA[e][1] = cA.y;
            accB[e][0] = cB.x; accB[e][1] = cB.y;
        }
    }

    #pragma unroll
    for (int k = 0; k < EF; k++) {
        ulonglong2 wA = *(const ulonglong2*)&sW[k][nA];      // conflict-free LDS.128
        ulonglong2 wB = *(const ulonglong2*)&sW[k][nB];
        float4 a0 = *(const float4*)&sA[k][eg * 8];          // broadcast LDS.128
        float4 a1 = *(const float4*)&sA[k][eg * 8 + 4];
        float av[8] = {a0.x, a0.y, a0.z, a0.w, a1.x, a1.y, a1.z, a1.w};
        #pragma unroll
        for (int e = 0; e < 8; e++) {
            ull ae = pack2(av[e]);
            fma2(accA[e][0], ae, wA.x);
            fma2(accA[e][1], ae, wA.y);
            fma2(accB[e][0], ae, wB.x);
            fma2(accB[e][1], ae, wB.y);
        }
    }

    // epilogue: partial z = sum relu(h)*w2 over 4 outputs per chunk
    float4 w2A = *(const float4*)&sV[nA];
    float4 w2B = *(const float4*)&sV[nB];
    float pzA[8], pzB[8];
    #pragma unroll
    for (int e = 0; e < 8; e++) {
        float l0, h0, l1, h1;
        unpack2(accA[e][0], l0, h0); unpack2(accA[e][1], l1, h1);
        pzA[e] = fmaxf(l0, 0.f) * w2A.x + fmaxf(h0, 0.f) * w2A.y
               + fmaxf(l1, 0.f) * w2A.z + fmaxf(h1, 0.f) * w2A.w;
        unpack2(accB[e][0], l0, h0); unpack2(accB[e][1], l1, h1);
        pzB[e] = fmaxf(l0, 0.f) * w2B.x + fmaxf(h0, 0.f) * w2B.y
               + fmaxf(l1, 0.f) * w2B.z + fmaxf(h1, 0.f) * w2B.w;
    }
    // reduce across the 16 lanes of each half-warp (layer group)
    #pragma unroll
    for (int off = 1; off < 16; off <<= 1) {
        #pragma unroll
        for (int e = 0; e < 8; e++) {
            pzA[e] += __shfl_xor_sync(0xffffffffu, pzA[e], off);
            pzB[e] += __shfl_xor_sync(0xffffffffu, pzB[e], off);
        }
    }
    if ((ng & 15) == 0) {
        int lA = ng >> 4;          // 0 or 1
        int lB = 2 + lA;           // 2 or 3
        float bA = sB[lA], bB = sB[lB];
        #pragma unroll
        for (int e = 0; e < 8; e++) {
            int eglob = blockIdx.x * 64 + eg * 8 + e;
            int c = clampi(colp[eglob], NN);
            float gA = 1.f / (1.f + __expf(-(pzA[e] + bA)));
            float gB = 1.f / (1.f + __expf(-(pzB[e] + bB)));
            ((float*)&g_gate[eglob])[lA] = gA;
            ((float*)&g_gate[eglob])[lB] = gB;
            atomicAdd(&g_deg[lA * NN + c], gA);
            atomicAdd(&g_deg[lB * NN + c], gB);
        }
    }
}

__global__ void k_scan1() {
    __shared__ int sh[256];
    int tid = threadIdx.x;
    int i = blockIdx.x * 256 + tid;
    int v = (i < NN) ? g_cnt[i] : 0;
    sh[tid] = v; __syncthreads();
    #pragma unroll
    for (int off = 1; off < 256; off <<= 1) {
        int t = (tid >= off) ? sh[tid - off] : 0;
        __syncthreads();
        sh[tid] += t;
        __syncthreads();
    }
    if (i < NN) g_tmp[i] = sh[tid] - v;
    if (tid == 255) g_bsum[blockIdx.x] = sh[255];
}

__global__ void k_scan2() {
    __shared__ int sh[256];
    int tid = threadIdx.x;
    int v = (tid < NSCB) ? g_bsum[tid] : 0;
    sh[tid] = v; __syncthreads();
    #pragma unroll
    for (int off = 1; off < 256; off <<= 1) {
        int t = (tid >= off) ? sh[tid - off] : 0;
        __syncthreads();
        sh[tid] += t;
        __syncthreads();
    }
    g_boff[tid] = sh[tid] - v;
}

__global__ void k_scan3() {
    int i = blockIdx.x * 256 + threadIdx.x;
    if (i < NN) {
        int r = g_tmp[i] + g_boff[blockIdx.x];
        g_rowptr[i] = r;
        g_pos[i] = r;
    }
    if (i == 0) g_rowptr[NN] = NE;
}

__global__ void k_scatter(const int* __restrict__ rowp,
                          const int* __restrict__ colp) {
    int e = blockIdx.x * blockDim.x + threadIdx.x;
    if (e >= NE) return;
    int c = clampi(colp[e], NN);
    int p = atomicAdd(&g_pos[c], 1);
    p = clampi(p, NE);
    g_se[p] = make_int2(clampi(rowp[e], NN), e);
}

// ---------------- h' = rsqrt(deg+1) * (x @ W), warp per row, f32x2 ----------------
__global__ __launch_bounds__(256) void k_gemm(const float* __restrict__ xin,
                                              const float* __restrict__ W,
                                              const float* __restrict__ degl) {
    __shared__ __align__(16) float sWf[HID * HID];
    for (int i = threadIdx.x; i < HID * HID; i += 256) sWf[i] = W[i];
    __syncthreads();
    int w = (blockIdx.x * 256 + threadIdx.x) >> 5;
    int lane = threadIdx.x & 31;
    if (w >= NN) return;
    float2 xv = *(const float2*)&xin[(size_t)w * HID + lane * 2];
    const ull* sW = (const ull*)sWf;
    ull acc = 0;
    #pragma unroll
    for (int k = 0; k < HID; k++) {
        float xk = __shfl_sync(0xffffffffu, (k & 1) ? xv.y : xv.x, k >> 1);
        fma2(acc, pack2(xk), sW[k * 32 + lane]);
    }
    float d = rsqrtf(degl[w] + 1.f);
    float lo, hi; unpack2(acc, lo, hi);
    *(float2*)&g_h[(size_t)w * HID + lane * 2] = make_float2(lo * d, hi * d);
}

// ---------------- SpMM: out[c] = disc*(sum ew*h'[src] + h'[c]) + b ----------------
__global__ __launch_bounds__(256) void k_spmm(const float* __restrict__ degl,
                                              const float* __restrict__ bias,
                                              float* __restrict__ xout,
                                              int l, int dorelu) {
    int c = (blockIdx.x * blockDim.x + threadIdx.x) >> 5;
    int lane = threadIdx.x & 31;
    if (c >= NN) return;
    int rs = g_rowptr[c], re = g_rowptr[c + 1];
    ull acc = 0;
    #pragma unroll 4
    for (int p = rs; p < re; p++) {
        int2 se = g_se[p];
        float ew = ((const float*)&g_gate[se.y])[l];
        ull hvp = *(const ull*)&g_h[(size_t)se.x * HID + lane * 2];
        fma2(acc, pack2(ew), hvp);
    }
    {   // self loop: + h'[c]
        ull hvp = *(const ull*)&g_h[(size_t)c * HID + lane * 2];
        fma2(acc, pack2(1.f), hvp);
    }
    float disc = rsqrtf(degl[c] + 1.f);
    float lo, hi; unpack2(acc, lo, hi);
    float2 b = *(const float2*)&bias[lane * 2];
    lo = lo * disc + b.x; hi = hi * disc + b.y;
    if (dorelu) { lo = fmaxf(lo, 0.f); hi = fmaxf(hi, 0.f); }
    *(float2*)&xout[(size_t)c * HID + lane * 2] = make_float2(lo, hi);
}

// ---------------- classifier + softmax at picked nodes ----------------
__global__ __launch_bounds__(128) void k_final(const float* __restrict__ xin,
                                               const float* __restrict__ linW,
                                               const float* __restrict__ linb,
                                               const int* __restrict__ pick,
                                               float* __restrict__ out) {
    __shared__ float sW[HID * NC];
    __shared__ float sb[NC];
    for (int i = threadIdx.x; i < HID * NC; i += 128) sW[i] = linW[i];
    if (threadIdx.x < NC) sb[threadIdx.x] = linb[threadIdx.x];
    __syncthreads();
    int t = blockIdx.x * 128 + threadIdx.x;
    if (t >= NPICK) return;
    int node = clampi(pick[t], NN);
    float lg[NC];
    #pragma unroll
    for (int j = 0; j < NC; j++) lg[j] = sb[j];
    const float4* xr = (const float4*)&xin[(size_t)node * HID];
    #pragma unroll
    for (int k4 = 0; k4 < 16; k4++) {
        float4 v = xr[k4];
        float xs[4] = {v.x, v.y, v.z, v.w};
        #pragma unroll
        for (int q = 0; q < 4; q++) {
            #pragma unroll
            for (int j = 0; j < NC; j++) lg[j] += xs[q] * sW[(k4 * 4 + q) * NC + j];
        }
    }
    float m = lg[0];
    #pragma unroll
    for (int j = 1; j < NC; j++) m = fmaxf(m, lg[j]);
    float ex[NC], s = 0.f;
    #pragma unroll
    for (int j = 0; j < NC; j++) { ex[j] = __expf(lg[j] - m); s += ex[j]; }
    float inv = 1.f / s;
    #pragma unroll
    for (int j = 0; j < NC; j++) out[(size_t)t * NC + j] = ex[j] * inv;
}

// ---------------- launch ----------------
extern "C" void kernel_launch(void* const* d_in, const int* in_sizes, int n_in,
                              void* d_out, int out_size) {
    const float* x      = (const float*)d_in[0];
    const float* eattr  = (const float*)d_in[1];
    const float* encW1  = (const float*)d_in[2];
    const float* encb1  = (const float*)d_in[3];
    const float* encW2  = (const float*)d_in[4];
    const float* encb2  = (const float*)d_in[5];
    const float* convW  = (const float*)d_in[6];
    const float* convB  = (const float*)d_in[7];
    const float* mlpW1  = (const float*)d_in[8];
    const float* mlpb1  = (const float*)d_in[9];
    const float* mlpW2  = (const float*)d_in[10];
    const float* mlpb2  = (const float*)d_in[11];
    const float* linW   = (const float*)d_in[12];
    const float* linb   = (const float*)d_in[13];
    const int* eidx     = (const int*)d_in[14];   // int32 (JAX x64 disabled)
    const int* pick     = (const int*)d_in[15];
    float* out = (float*)d_out;

    const int* rowp = eidx;
    const int* colp = eidx + NE;

    float *xa, *xb, *deg;
    cudaGetSymbolAddress((void**)&xa, g_xa);
    cudaGetSymbolAddress((void**)&xb, g_xb);
    cudaGetSymbolAddress((void**)&deg, g_deg);

    const int EB = (NE + 255) / 256;        // 3125
    const int WB = (NN * 32 + 255) / 256;   // 6250

    // launch index 0..2
    k_fold<<<1, 256>>>(encW1, encb1, encW2, encb2, mlpW1, mlpb1);
    k_zero<<<(4 * NN + 255) / 256, 256>>>();
    k_count<<<EB, 256>>>(colp);

    // launch index 3: k_edge (lands in the ncu -s window)
    k_edge<<<EBLK, 256>>>(eattr, colp, mlpW2, mlpb2);

    // CSR scan + scatter
    k_scan1<<<NSCB, 256>>>();
    k_scan2<<<1, 256>>>();
    k_scan3<<<NSCB, 256>>>();
    k_scatter<<<EB, 256>>>(rowp, colp);

    const float* xin = x;
    float* bufs[2] = { xa, xb };
    for (int l = 0; l < 4; l++) {
        k_gemm<<<WB, 256>>>(xin, convW + l * HID * HID, deg + l * NN);
        k_spmm<<<WB, 256>>>(deg + l * NN, convB + l * HID, bufs[l & 1], l, (l < 3) ? 1 : 0);
        xin = bufs[l & 1];
    }

    k_final<<<32, 128>>>(xin, linW, linb, pick, out);
}

// round 10
// speedup vs baseline: 1.1987x; 1.0506x over previous
#include <cuda_runtime.h>
#include <math.h>
#include <stdint.h>

#define NN     50000
#define NE     800000
#define EF     16
#define HID    64
#define NC     10
#define NPICK  4096
#define NSCB   196            // ceil(NN/256)
#define EPB    48             // edges per block in k_edge
#define EBLK   16667          // ceil(NE/EPB)

typedef unsigned long long ull;

// ---------------- scratch (static device globals; no allocation) ----------------
__device__ float  g_M[EF * 256];         // folded gate weights, swizzled [k][p(n)]
__device__ float  g_c[256];              // folded gate bias, swizzled [p(n)]
__device__ float4 g_gate[NE];            // 4 per-layer gates, edge-id order
__device__ float  g_deg[4 * NN];         // per-layer degree sums (atomic)
__device__ __align__(256) float g_h[NN * HID];    // h' = dis * (x @ W)
__device__ __align__(256) float g_xa[NN * HID];
__device__ __align__(256) float g_xb[NN * HID];
__device__ int    g_cnt[NN];
__device__ int    g_tmp[NN];
__device__ int    g_bsum[256];
__device__ int    g_boff[256];
__device__ int    g_rowptr[NN + 1];
__device__ int    g_pos[NN];
__device__ int2   g_se[NE];              // CSR: (src node, edge id) per slot

__device__ __forceinline__ int clampi(int v, int hi) {
    return v < 0 ? 0 : (v >= hi ? hi - 1 : v);
}
__device__ __forceinline__ ull pack2(float x) {
    ull r; unsigned int b = __float_as_uint(x);
    asm("mov.b64 %0, {%1, %2};" : "=l"(r) : "r"(b), "r"(b));
    return r;
}
__device__ __forceinline__ void fma2(ull& d, ull a, ull b) {
    asm("fma.rn.f32x2 %0, %1, %2, %0;" : "+l"(d) : "l"(a), "l"(b));
}
__device__ __forceinline__ void unpack2(ull v, float& lo, float& hi) {
    unsigned int l, h;
    asm("mov.b64 {%0, %1}, %2;" : "=r"(l), "=r"(h) : "l"(v));
    lo = __uint_as_float(l); hi = __uint_as_float(h);
}
// output-index swizzle: thread ng's 8 outputs (n = 8*ng .. 8*ng+7) live at
// words 4*ng+{0..3} and 128+4*ng+{0..3} -> both LDS.128 at the 4-phase floor.
__device__ __forceinline__ int swzn(int n) {
    int ng = n >> 3, i = n & 7;
    return (i < 4) ? (4 * ng + i) : (128 + 4 * ng + (i - 4));
}

// ---------------- weight folding: M = (encW1@encW2)@mlpW1, swizzled layout ----------------
__global__ __launch_bounds__(256) void k_fold(
    const float* __restrict__ encW1, const float* __restrict__ encb1,
    const float* __restrict__ encW2, const float* __restrict__ encb2,
    const float* __restrict__ mlpW1, const float* __restrict__ mlpb1)
{
    __shared__ float sW1[256], sW2[256], sWc[256], sbc[16];
    int tid = threadIdx.x;
    sW1[tid] = encW1[tid];
    sW2[tid] = encW2[tid];
    __syncthreads();
    {   // Wc = W1 @ W2 (16x16)
        int i = tid >> 4, j = tid & 15;
        float s = 0.f;
        #pragma unroll
        for (int k = 0; k < EF; k++) s += sW1[i * EF + k] * sW2[k * EF + j];
        sWc[tid] = s;
    }
    if (tid < EF) {
        float s = encb2[tid];
        #pragma unroll
        for (int k = 0; k < EF; k++) s += encb1[k] * sW2[k * EF + tid];
        sbc[tid] = s;
    }
    __syncthreads();
    #pragma unroll 1
    for (int m = 0; m < 16; m++) {
        int idx = tid + 256 * m;                 // 0..4095
        int l = idx >> 10, k = (idx >> 6) & 15, j = idx & 63;
        float s = 0.f;
        #pragma unroll
        for (int i = 0; i < EF; i++) s += sWc[k * EF + i] * mlpW1[(l * EF + i) * HID + j];
        g_M[k * 256 + swzn(l * 64 + j)] = s;
    }
    {
        int l = tid >> 6, j = tid & 63;
        float s = mlpb1[l * HID + j];
        #pragma unroll
        for (int i = 0; i < EF; i++) s += sbc[i] * mlpW1[(l * EF + i) * HID + j];
        g_c[swzn(tid)] = s;
    }
}

// ---------------- zero counters ----------------
__global__ void k_zero() {
    int i = blockIdx.x * blockDim.x + threadIdx.x;
    if (i < 4 * NN) g_deg[i] = 0.f;
    if (i < NN) g_cnt[i] = 0;
}

// ---------------- CSR build ----------------
__global__ void k_count(const int* __restrict__ colp) {
    int e = blockIdx.x * blockDim.x + threadIdx.x;
    if (e < NE) atomicAdd(&g_cnt[clampi(colp[e], NN)], 1);
}

// ---------------- tiled edge-gate GEMM: 48 edges x 256 outputs per block ----------------
// thread tile: 6 edges x 8 outputs (one layer, swizzled two 16B weight chunks).
// eg = tid>>5 (8 groups x 6 edges), ng = tid&31: layer = ng>>3.
__global__ __launch_bounds__(256, 3) void k_edge(const float* __restrict__ eattr,
                                                 const int* __restrict__ colp,
                                                 const float* __restrict__ mlpW2,
                                                 const float* __restrict__ mlpb2)
{
    __shared__ __align__(16) ull   sAp[EF][EPB];   // packed-dup edge values: 6 KB
    __shared__ __align__(16) float sW[EF * 256];   // swizzled folded M: 16 KB
    __shared__ __align__(16) float sC[256];        // swizzled folded bias
    __shared__ __align__(16) float sV[256];        // swizzled mlpW2
    __shared__ float sB[4];

    int tid = threadIdx.x;
    {   // weights: 16 KB straight copy (already swizzled by k_fold)
        const float4* src = (const float4*)g_M;
        float4* dst = (float4*)sW;
        #pragma unroll
        for (int i = 0; i < 4; i++) dst[tid + 256 * i] = src[tid + 256 * i];
    }
    sC[tid] = g_c[tid];
    sV[swzn(tid)] = mlpW2[tid];
    if (tid < 4) sB[tid] = mlpb2[tid];
    if (tid < 4 * EPB) {   // a-tile: 48 edges x 16 floats, packed+transposed
        int e = tid >> 2, q = tid & 3;
        int eglob = blockIdx.x * EPB + e;
        if (eglob >= NE) eglob = NE - 1;
        float4 v = ((const float4*)(eattr + (size_t)eglob * EF))[q];
        sAp[q * 4 + 0][e] = pack2(v.x);
        sAp[q * 4 + 1][e] = pack2(v.y);
        sAp[q * 4 + 2][e] = pack2(v.z);
        sAp[q * 4 + 3][e] = pack2(v.w);
    }
    __syncthreads();

    const int eg = tid >> 5;        // edges 6*eg .. 6*eg+5
    const int ng = tid & 31;
    const int pA = 4 * ng;          // swizzled chunk A (n = 8ng..8ng+3)
    const int pB = 128 + 4 * ng;    // swizzled chunk B (n = 8ng+4..8ng+7)

    ull accA[6][2], accB[6][2];
    {
        ulonglong2 cA = *(const ulonglong2*)&sC[pA];
        ulonglong2 cB = *(const ulonglong2*)&sC[pB];
        #pragma unroll
        for (int e = 0; e < 6; e++) {
            accA[e][0] = cA.x; accA[e][1] = cA.y;
            accB[e][0] = cB.x; accB[e][1] = cB.y;
        }
    }

    #pragma unroll
    for (int k = 0; k < EF; k++) {
        ulonglong2 wA = *(const ulonglong2*)&sW[k * 256 + pA];   // 4-phase floor
        ulonglong2 wB = *(const ulonglong2*)&sW[k * 256 + pB];   // 4-phase floor
        ulonglong2 a01 = *(const ulonglong2*)&sAp[k][eg * 6];    // broadcast
        ulonglong2 a23 = *(const ulonglong2*)&sAp[k][eg * 6 + 2];
        ulonglong2 a45 = *(const ulonglong2*)&sAp[k][eg * 6 + 4];
        ull av[6] = {a01.x, a01.y, a23.x, a23.y, a45.x, a45.y};
        #pragma unroll
        for (int e = 0; e < 6; e++) {
            fma2(accA[e][0], av[e], wA.x);
            fma2(accA[e][1], av[e], wA.y);
            fma2(accB[e][0], av[e], wB.x);
            fma2(accB[e][1], av[e], wB.y);
        }
    }

    // epilogue: z-partials over this thread's 8 outputs (single layer)
    float4 w2A = *(const float4*)&sV[pA];
    float4 w2B = *(const float4*)&sV[pB];
    float pz[6];
    #pragma unroll
    for (int e = 0; e < 6; e++) {
        float h0, h1, h2, h3, h4, h5, h6, h7;
        unpack2(accA[e][0], h0, h1); unpack2(accA[e][1], h2, h3);
        unpack2(accB[e][0], h4, h5); unpack2(accB[e][1], h6, h7);
        pz[e] = fmaxf(h0, 0.f) * w2A.x + fmaxf(h1, 0.f) * w2A.y
              + fmaxf(h2, 0.f) * w2A.z + fmaxf(h3, 0.f) * w2A.w
              + fmaxf(h4, 0.f) * w2B.x + fmaxf(h5, 0.f) * w2B.y
              + fmaxf(h6, 0.f) * w2B.z + fmaxf(h7, 0.f) * w2B.w;
    }
    // 8-lane reduction within layer group
    #pragma unroll
    for (int off = 1; off < 8; off <<= 1) {
        #pragma unroll
        for (int e = 0; e < 6; e++)
            pz[e] += __shfl_xor_sync(0xffffffffu, pz[e], off);
    }
    if ((ng & 7) == 0) {
        int l = ng >> 3;
        float bl = sB[l];
        #pragma unroll
        for (int e = 0; e < 6; e++) {
            int eglob = blockIdx.x * EPB + eg * 6 + e;
            if (eglob < NE) {
                float g = 1.f / (1.f + __expf(-(pz[e] + bl)));
                ((float*)&g_gate[eglob])[l] = g;
                atomicAdd(&g_deg[l * NN + clampi(colp[eglob], NN)], g);
            }
        }
    }
}

__global__ void k_scan1() {
    __shared__ int sh[256];
    int tid = threadIdx.x;
    int i = blockIdx.x * 256 + tid;
    int v = (i < NN) ? g_cnt[i] : 0;
    sh[tid] = v; __syncthreads();
    #pragma unroll
    for (int off = 1; off < 256; off <<= 1) {
        int t = (tid >= off) ? sh[tid - off] : 0;
        __syncthreads();
        sh[tid] += t;
        __syncthreads();
    }
    if (i < NN) g_tmp[i] = sh[tid] - v;
    if (tid == 255) g_bsum[blockIdx.x] = sh[255];
}

__global__ void k_scan2() {
    __shared__ int sh[256];
    int tid = threadIdx.x;
    int v = (tid < NSCB) ? g_bsum[tid] : 0;
    sh[tid] = v; __syncthreads();
    #pragma unroll
    for (int off = 1; off < 256; off <<= 1) {
        int t = (tid >= off) ? sh[tid - off] : 0;
        __syncthreads();
        sh[tid] += t;
        __syncthreads();
    }
    g_boff[tid] = sh[tid] - v;
}

__global__ void k_scan3() {
    int i = blockIdx.x * 256 + threadIdx.x;
    if (i < NN) {
        int r = g_tmp[i] + g_boff[blockIdx.x];
        g_rowptr[i] = r;
        g_pos[i] = r;
    }
    if (i == 0) g_rowptr[NN] = NE;
}

__global__ void k_scatter(const int* __restrict__ rowp,
                          const int* __restrict__ colp) {
    int e = blockIdx.x * blockDim.x + threadIdx.x;
    if (e >= NE) return;
    int c = clampi(colp[e], NN);
    int p = atomicAdd(&g_pos[c], 1);
    p = clampi(p, NE);
    g_se[p] = make_int2(clampi(rowp[e], NN), e);
}

// ---------------- h' = rsqrt(deg+1) * (x @ W), warp per row, f32x2 ----------------
__global__ __launch_bounds__(256) void k_gemm(const float* __restrict__ xin,
                                              const float* __restrict__ W,
                                              const float* __restrict__ degl) {
    __shared__ __align__(16) float sWf[HID * HID];
    for (int i = threadIdx.x; i < HID * HID; i += 256) sWf[i] = W[i];
    __syncthreads();
    int w = (blockIdx.x * 256 + threadIdx.x) >> 5;
    int lane = threadIdx.x & 31;
    if (w >= NN) return;
    float2 xv = *(const float2*)&xin[(size_t)w * HID + lane * 2];
    const ull* sW = (const ull*)sWf;
    ull acc = 0;
    #pragma unroll
    for (int k = 0; k < HID; k++) {
        float xk = __shfl_sync(0xffffffffu, (k & 1) ? xv.y : xv.x, k >> 1);
        fma2(acc, pack2(xk), sW[k * 32 + lane]);
    }
    float d = rsqrtf(degl[w] + 1.f);
    float lo, hi; unpack2(acc, lo, hi);
    *(float2*)&g_h[(size_t)w * HID + lane * 2] = make_float2(lo * d, hi * d);
}

// ---------------- SpMM: out[c] = disc*(sum ew*h'[src] + h'[c]) + b ----------------
__global__ __launch_bounds__(256) void k_spmm(const float* __restrict__ degl,
                                              const float* __restrict__ bias,
                                              float* __restrict__ xout,
                                              int l, int dorelu) {
    int c = (blockIdx.x * blockDim.x + threadIdx.x) >> 5;
    int lane = threadIdx.x & 31;
    if (c >= NN) return;
    int rs = g_rowptr[c], re = g_rowptr[c + 1];
    ull acc = 0;
    #pragma unroll 4
    for (int p = rs; p < re; p++) {
        int2 se = g_se[p];
        float ew = ((const float*)&g_gate[se.y])[l];
        ull hvp = *(const ull*)&g_h[(size_t)se.x * HID + lane * 2];
        fma2(acc, pack2(ew), hvp);
    }
    {   // self loop: + h'[c]
        ull hvp = *(const ull*)&g_h[(size_t)c * HID + lane * 2];
        fma2(acc, pack2(1.f), hvp);
    }
    float disc = rsqrtf(degl[c] + 1.f);
    float lo, hi; unpack2(acc, lo, hi);
    float2 b = *(const float2*)&bias[lane * 2];
    lo = lo * disc + b.x; hi = hi * disc + b.y;
    if (dorelu) { lo = fmaxf(lo, 0.f); hi = fmaxf(hi, 0.f); }
    *(float2*)&xout[(size_t)c * HID + lane * 2] = make_float2(lo, hi);
}

// ---------------- classifier + softmax at picked nodes ----------------
__global__ __launch_bounds__(128) void k_final(const float* __restrict__ xin,
                                               const float* __restrict__ linW,
                                               const float* __restrict__ linb,
                                               const int* __restrict__ pick,
                                               float* __restrict__ out) {
    __shared__ float sW[HID * NC];
    __shared__ float sb[NC];
    for (int i = threadIdx.x; i < HID * NC; i += 128) sW[i] = linW[i];
    if (threadIdx.x < NC) sb[threadIdx.x] = linb[threadIdx.x];
    __syncthreads();
    int t = blockIdx.x * 128 + threadIdx.x;
    if (t >= NPICK) return;
    int node = clampi(pick[t], NN);
    float lg[NC];
    #pragma unroll
    for (int j = 0; j < NC; j++) lg[j] = sb[j];
    const float4* xr = (const float4*)&xin[(size_t)node * HID];
    #pragma unroll
    for (int k4 = 0; k4 < 16; k4++) {
        float4 v = xr[k4];
        float xs[4] = {v.x, v.y, v.z, v.w};
        #pragma unroll
        for (int q = 0; q < 4; q++) {
            #pragma unroll
            for (int j = 0; j < NC; j++) lg[j] += xs[q] * sW[(k4 * 4 + q) * NC + j];
        }
    }
    float m = lg[0];
    #pragma unroll
    for (int j = 1; j < NC; j++) m = fmaxf(m, lg[j]);
    float ex[NC], s = 0.f;
    #pragma unroll
    for (int j = 0; j < NC; j++) { ex[j] = __expf(lg[j] - m); s += ex[j]; }
    float inv = 1.f / s;
    #pragma unroll
    for (int j = 0; j < NC; j++) out[(size_t)t * NC + j] = ex[j] * inv;
}

// ---------------- launch ----------------
extern "C" void kernel_launch(void* const* d_in, const int* in_sizes, int n_in,
                              void* d_out, int out_size) {
    const float* x      = (const float*)d_in[0];
    const float* eattr  = (const float*)d_in[1];
    const float* encW1  = (const float*)d_in[2];
    const float* encb1  = (const float*)d_in[3];
    const float* encW2  = (const float*)d_in[4];
    const float* encb2  = (const float*)d_in[5];
    const float* convW  = (const float*)d_in[6];
    const float* convB  = (const float*)d_in[7];
    const float* mlpW1  = (const float*)d_in[8];
    const float* mlpb1  = (const float*)d_in[9];
    const float* mlpW2  = (const float*)d_in[10];
    const float* mlpb2  = (const float*)d_in[11];
    const float* linW   = (const float*)d_in[12];
    const float* linb   = (const float*)d_in[13];
    const int* eidx     = (const int*)d_in[14];   // int32 (JAX x64 disabled)
    const int* pick     = (const int*)d_in[15];
    float* out = (float*)d_out;

    const int* rowp = eidx;
    const int* colp = eidx + NE;

    float *xa, *xb, *deg;
    cudaGetSymbolAddress((void**)&xa, g_xa);
    cudaGetSymbolAddress((void**)&xb, g_xb);
    cudaGetSymbolAddress((void**)&deg, g_deg);

    const int EB = (NE + 255) / 256;        // 3125
    const int WB = (NN * 32 + 255) / 256;   // 6250

    // launch index 0..2
    k_fold<<<1, 256>>>(encW1, encb1, encW2, encb2, mlpW1, mlpb1);
    k_zero<<<(4 * NN + 255) / 256, 256>>>();
    k_count<<<EB, 256>>>(colp);

    // launch index 3: k_edge (lands in the ncu -s window)
    k_edge<<<EBLK, 256>>>(eattr, colp, mlpW2, mlpb2);

    // CSR scan + scatter
    k_scan1<<<NSCB, 256>>>();
    k_scan2<<<1, 256>>>();
    k_scan3<<<NSCB, 256>>>();
    k_scatter<<<EB, 256>>>(rowp, colp);

    const float* xin = x;
    float* bufs[2] = { xa, xb };
    for (int l = 0; l < 4; l++) {
        k_gemm<<<WB, 256>>>(xin, convW + l * HID * HID, deg + l * NN);
        k_spmm<<<WB, 256>>>(deg + l * NN, convB + l * HID, bufs[l & 1], l, (l < 3) ? 1 : 0);
        xin = bufs[l & 1];
    }

    k_final<<<32, 128>>>(xin, linW, linb, pick, out);
}

// round 13
// speedup vs baseline: 1.2474x; 1.0406x over previous
#include <cuda_runtime.h>
#include <math.h>
#include <stdint.h>

#define NN     50000
#define NE     800000
#define EF     16
#define HID    64
#define NC     10
#define NPICK  4096
#define NSCB   196            // ceil(NN/256)
#define EPB    48             // edges per block in k_edge
#define EBLK   16667          // ceil(NE/EPB)

typedef unsigned long long ull;

// ---------------- scratch (static device globals; no allocation) ----------------
__device__ float  g_M[EF * 256];         // folded gate weights, swizzled [k][p(n)]
__device__ float  g_c[256];              // folded gate bias, swizzled [p(n)]
__device__ float4 g_gate[NE];            // 4 per-layer gates, edge-id order
__device__ float  g_deg[4 * NN];         // per-layer degree sums (atomic)
__device__ __align__(256) float g_h[NN * HID];    // h' = dis * (x @ W)
__device__ __align__(256) float g_xa[NN * HID];
__device__ __align__(256) float g_xb[NN * HID];
__device__ int    g_cnt[NN];
__device__ int    g_tmp[NN];
__device__ int    g_bsum[256];
__device__ int    g_boff[256];
__device__ int    g_rowptr[NN + 1];
__device__ int    g_pos[NN];
__device__ int2   g_se[NE];              // CSR: (src node, edge id) per slot

__device__ __forceinline__ int clampi(int v, int hi) {
    return v < 0 ? 0 : (v >= hi ? hi - 1 : v);
}
__device__ __forceinline__ ull pack2(float x) {
    ull r; unsigned int b = __float_as_uint(x);
    asm("mov.b64 %0, {%1, %2};" : "=l"(r) : "r"(b), "r"(b));
    return r;
}
__device__ __forceinline__ void fma2(ull& d, ull a, ull b) {
    asm("fma.rn.f32x2 %0, %1, %2, %0;" : "+l"(d) : "l"(a), "l"(b));
}
__device__ __forceinline__ void unpack2(ull v, float& lo, float& hi) {
    unsigned int l, h;
    asm("mov.b64 {%0, %1}, %2;" : "=r"(l), "=r"(h) : "l"(v));
    lo = __uint_as_float(l); hi = __uint_as_float(h);
}
// output-index swizzle: thread ng's 8 outputs (n = 8*ng .. 8*ng+7) live at
// words 4*ng+{0..3} and 128+4*ng+{0..3} -> both LDS.128 at the 4-phase floor.
__device__ __forceinline__ int swzn(int n) {
    int ng = n >> 3, i = n & 7;
    return (i < 4) ? (4 * ng + i) : (128 + 4 * ng + (i - 4));
}

// ---------------- weight folding: M = (encW1@encW2)@mlpW1, swizzled layout ----------------
__global__ __launch_bounds__(256) void k_fold(
    const float* __restrict__ encW1, const float* __restrict__ encb1,
    const float* __restrict__ encW2, const float* __restrict__ encb2,
    const float* __restrict__ mlpW1, const float* __restrict__ mlpb1)
{
    __shared__ float sW1[256], sW2[256], sWc[256], sbc[16];
    int tid = threadIdx.x;
    sW1[tid] = encW1[tid];
    sW2[tid] = encW2[tid];
    __syncthreads();
    {   // Wc = W1 @ W2 (16x16)
        int i = tid >> 4, j = tid & 15;
        float s = 0.f;
        #pragma unroll
        for (int k = 0; k < EF; k++) s += sW1[i * EF + k] * sW2[k * EF + j];
        sWc[tid] = s;
    }
    if (tid < EF) {
        float s = encb2[tid];
        #pragma unroll
        for (int k = 0; k < EF; k++) s += encb1[k] * sW2[k * EF + tid];
        sbc[tid] = s;
    }
    __syncthreads();
    #pragma unroll 1
    for (int m = 0; m < 16; m++) {
        int idx = tid + 256 * m;                 // 0..4095
        int l = idx >> 10, k = (idx >> 6) & 15, j = idx & 63;
        float s = 0.f;
        #pragma unroll
        for (int i = 0; i < EF; i++) s += sWc[k * EF + i] * mlpW1[(l * EF + i) * HID + j];
        g_M[k * 256 + swzn(l * 64 + j)] = s;
    }
    {
        int l = tid >> 6, j = tid & 63;
        float s = mlpb1[l * HID + j];
        #pragma unroll
        for (int i = 0; i < EF; i++) s += sbc[i] * mlpW1[(l * EF + i) * HID + j];
        g_c[swzn(tid)] = s;
    }
}

// ---------------- zero counters ----------------
__global__ void k_zero() {
    int i = blockIdx.x * blockDim.x + threadIdx.x;
    if (i < 4 * NN) g_deg[i] = 0.f;
    if (i < NN) g_cnt[i] = 0;
}

// ---------------- CSR build ----------------
__global__ void k_count(const int* __restrict__ colp) {
    int e = blockIdx.x * blockDim.x + threadIdx.x;
    if (e < NE) atomicAdd(&g_cnt[clampi(colp[e], NN)], 1);
}

// ---------------- tiled edge-gate GEMM: 48 edges x 256 outputs per block ----------------
// thread tile: 6 edges x 8 outputs (one layer, swizzled two 16B weight chunks).
// eg = tid>>5 (8 groups x 6 edges), ng = tid&31: layer = ng>>3.
__global__ __launch_bounds__(256, 3) void k_edge(const float* __restrict__ eattr,
                                                 const int* __restrict__ colp,
                                                 const float* __restrict__ mlpW2,
                                                 const float* __restrict__ mlpb2)
{
    __shared__ __align__(16) ull   sAp[EF][EPB];   // packed-dup edge values: 6 KB
    __shared__ __align__(16) float sW[EF * 256];   // swizzled folded M: 16 KB
    __shared__ __align__(16) float sC[256];        // swizzled folded bias
    __shared__ __align__(16) float sV[256];        // swizzled mlpW2
    __shared__ float sB[4];

    int tid = threadIdx.x;
    {   // weights: 16 KB straight copy (already swizzled by k_fold)
        const float4* src = (const float4*)g_M;
        float4* dst = (float4*)sW;
        #pragma unroll
        for (int i = 0; i < 4; i++) dst[tid + 256 * i] = src[tid + 256 * i];
    }
    sC[tid] = g_c[tid];
    sV[swzn(tid)] = mlpW2[tid];
    if (tid < 4) sB[tid] = mlpb2[tid];
    if (tid < 4 * EPB) {   // a-tile: 48 edges x 16 floats, packed+transposed
        int e = tid >> 2, q = tid & 3;
        int eglob = blockIdx.x * EPB + e;
        if (eglob >= NE) eglob = NE - 1;
        float4 v = ((const float4*)(eattr + (size_t)eglob * EF))[q];
        sAp[q * 4 + 0][e] = pack2(v.x);
        sAp[q * 4 + 1][e] = pack2(v.y);
        sAp[q * 4 + 2][e] = pack2(v.z);
        sAp[q * 4 + 3][e] = pack2(v.w);
    }
    __syncthreads();

    const int eg = tid >> 5;        // edges 6*eg .. 6*eg+5
    const int ng = tid & 31;
    const int pA = 4 * ng;          // swizzled chunk A (n = 8ng..8ng+3)
    const int pB = 128 + 4 * ng;    // swizzled chunk B (n = 8ng+4..8ng+7)

    ull accA[6][2], accB[6][2];
    {
        ulonglong2 cA = *(const ulonglong2*)&sC[pA];
        ulonglong2 cB = *(const ulonglong2*)&sC[pB];
        #pragma unroll
        for (int e = 0; e < 6; e++) {
            accA[e][0] = cA.x; accA[e][1] = cA.y;
            accB[e][0] = cB.x; accB[e][1] = cB.y;
        }
    }

    #pragma unroll
    for (int k = 0; k < EF; k++) {
        ulonglong2 wA = *(const ulonglong2*)&sW[k * 256 + pA];   // 4-phase floor
        ulonglong2 wB = *(const ulonglong2*)&sW[k * 256 + pB];   // 4-phase floor
        ulonglong2 a01 = *(const ulonglong2*)&sAp[k][eg * 6];    // broadcast
        ulonglong2 a23 = *(const ulonglong2*)&sAp[k][eg * 6 + 2];
        ulonglong2 a45 = *(const ulonglong2*)&sAp[k][eg * 6 + 4];
        ull av[6] = {a01.x, a01.y, a23.x, a23.y, a45.x, a45.y};
        #pragma unroll
        for (int e = 0; e < 6; e++) {
            fma2(accA[e][0], av[e], wA.x);
            fma2(accA[e][1], av[e], wA.y);
            fma2(accB[e][0], av[e], wB.x);
            fma2(accB[e][1], av[e], wB.y);
        }
    }

    // epilogue: z-partials over this thread's 8 outputs (single layer)
    float4 w2A = *(const float4*)&sV[pA];
    float4 w2B = *(const float4*)&sV[pB];
    float pz[6];
    #pragma unroll
    for (int e = 0; e < 6; e++) {
        float h0, h1, h2, h3, h4, h5, h6, h7;
        unpack2(accA[e][0], h0, h1); unpack2(accA[e][1], h2, h3);
        unpack2(accB[e][0], h4, h5); unpack2(accB[e][1], h6, h7);
        pz[e] = fmaxf(h0, 0.f) * w2A.x + fmaxf(h1, 0.f) * w2A.y
              + fmaxf(h2, 0.f) * w2A.z + fmaxf(h3, 0.f) * w2A.w
              + fmaxf(h4, 0.f) * w2B.x + fmaxf(h5, 0.f) * w2B.y
              + fmaxf(h6, 0.f) * w2B.z + fmaxf(h7, 0.f) * w2B.w;
    }
    // 8-lane reduction within layer group
    #pragma unroll
    for (int off = 1; off < 8; off <<= 1) {
        #pragma unroll
        for (int e = 0; e < 6; e++)
            pz[e] += __shfl_xor_sync(0xffffffffu, pz[e], off);
    }
    if ((ng & 7) == 0) {
        int l = ng >> 3;
        float bl = sB[l];
        #pragma unroll
        for (int e = 0; e < 6; e++) {
            int eglob = blockIdx.x * EPB + eg * 6 + e;
            if (eglob < NE) {
                float g = 1.f / (1.f + __expf(-(pz[e] + bl)));
                ((float*)&g_gate[eglob])[l] = g;
                atomicAdd(&g_deg[l * NN + clampi(colp[eglob], NN)], g);
            }
        }
    }
}

__global__ void k_scan1() {
    __shared__ int sh[256];
    int tid = threadIdx.x;
    int i = blockIdx.x * 256 + tid;
    int v = (i < NN) ? g_cnt[i] : 0;
    sh[tid] = v; __syncthreads();
    #pragma unroll
    for (int off = 1; off < 256; off <<= 1) {
        int t = (tid >= off) ? sh[tid - off] : 0;
        __syncthreads();
        sh[tid] += t;
        __syncthreads();
    }
    if (i < NN) g_tmp[i] = sh[tid] - v;
    if (tid == 255) g_bsum[blockIdx.x] = sh[255];
}

__global__ void k_scan2() {
    __shared__ int sh[256];
    int tid = threadIdx.x;
    int v = (tid < NSCB) ? g_bsum[tid] : 0;
    sh[tid] = v; __syncthreads();
    #pragma unroll
    for (int off = 1; off < 256; off <<= 1) {
        int t = (tid >= off) ? sh[tid - off] : 0;
        __syncthreads();
        sh[tid] += t;
        __syncthreads();
    }
    g_boff[tid] = sh[tid] - v;
}

__global__ void k_scan3() {
    int i = blockIdx.x * 256 + threadIdx.x;
    if (i < NN) {
        int r = g_tmp[i] + g_boff[blockIdx.x];
        g_rowptr[i] = r;
        g_pos[i] = r;
    }
    if (i == 0) g_rowptr[NN] = NE;
}

__global__ void k_scatter(const int* __restrict__ rowp,
                          const int* __restrict__ colp) {
    int e = blockIdx.x * blockDim.x + threadIdx.x;
    if (e >= NE) return;
    int c = clampi(colp[e], NN);
    int p = atomicAdd(&g_pos[c], 1);
    p = clampi(p, NE);
    g_se[p] = make_int2(clampi(rowp[e], NN), e);
}

// ---------------- h' = rsqrt(deg+1) * (x @ W), warp per row, f32x2 ----------------
__global__ __launch_bounds__(256) void k_gemm(const float* __restrict__ xin,
                                              const float* __restrict__ W,
                                              const float* __restrict__ degl) {
    __shared__ __align__(16) float sWf[HID * HID];
    for (int i = threadIdx.x; i < HID * HID; i += 256) sWf[i] = W[i];
    __syncthreads();
    int w = (blockIdx.x * 256 + threadIdx.x) >> 5;
    int lane = threadIdx.x & 31;
    if (w >= NN) return;
    float2 xv = *(const float2*)&xin[(size_t)w * HID + lane * 2];
    const ull* sW = (const ull*)sWf;
    ull acc = 0;
    #pragma unroll
    for (int k = 0; k < HID; k++) {
        float xk = __shfl_sync(0xffffffffu, (k & 1) ? xv.y : xv.x, k >> 1);
        fma2(acc, pack2(xk), sW[k * 32 + lane]);
    }
    float d = rsqrtf(degl[w] + 1.f);
    float lo, hi; unpack2(acc, lo, hi);
    *(float2*)&g_h[(size_t)w * HID + lane * 2] = make_float2(lo * d, hi * d);
}

// ---------------- SpMM (half-warp split): out[row] = disc*(sum ew*h'[src] + h'[c]) + b
// Each warp: one destination row. Half h processes edges p = rs+h, rs+h+2, ...;
// lane li (0..15) covers outputs 4*li..4*li+3. Halves combined with an f32x2 add
// (fma2 with multiplier 1.0 — NOT integer +=, packed floats!).
__global__ __launch_bounds__(256) void k_spmm(const float* __restrict__ degl,
                                              const float* __restrict__ bias,
                                              float* __restrict__ xout,
                                              int l, int dorelu,
                                              const int* __restrict__ pick, int nrows) {
    int w = (blockIdx.x * blockDim.x + threadIdx.x) >> 5;
    int lane = threadIdx.x & 31;
    int h = lane >> 4;
    int li = lane & 15;
    if (w >= nrows) return;
    int c = pick ? clampi(pick[w], NN) : w;
    int rs = g_rowptr[c], re = g_rowptr[c + 1];
    ull a0 = 0, a1 = 0;
    #pragma unroll 2
    for (int p = rs + h; p < re; p += 2) {
        int2 se = g_se[p];
        float ew = ((const float*)&g_gate[se.y])[l];
        ulonglong2 hv = *(const ulonglong2*)&g_h[(size_t)se.x * HID + li * 4];
        ull ewp = pack2(ew);
        fma2(a0, ewp, hv.x);
        fma2(a1, ewp, hv.y);
    }
    // combine halves as f32x2 (float add via fma2 with 1.0 multiplier)
    {
        ull one = pack2(1.f);
        ull t0 = __shfl_xor_sync(0xffffffffu, a0, 16);
        ull t1 = __shfl_xor_sync(0xffffffffu, a1, 16);
        fma2(a0, one, t0);
        fma2(a1, one, t1);
        // self loop: + h'[c]
        ulonglong2 hv = *(const ulonglong2*)&g_h[(size_t)c * HID + li * 4];
        fma2(a0, one, hv.x);
        fma2(a1, one, hv.y);
    }
    if (h == 0) {
        float disc = rsqrtf(degl[c] + 1.f);
        float o0, o1, o2, o3;
        unpack2(a0, o0, o1); unpack2(a1, o2, o3);
        float4 b = *(const float4*)&bias[li * 4];
        o0 = o0 * disc + b.x; o1 = o1 * disc + b.y;
        o2 = o2 * disc + b.z; o3 = o3 * disc + b.w;
        if (dorelu) {
            o0 = fmaxf(o0, 0.f); o1 = fmaxf(o1, 0.f);
            o2 = fmaxf(o2, 0.f); o3 = fmaxf(o3, 0.f);
        }
        *(float4*)&xout[(size_t)w * HID + li * 4] = make_float4(o0, o1, o2, o3);
    }
}

// ---------------- classifier + softmax on compacted picked rows ----------------
__global__ __launch_bounds__(128) void k_final(const float* __restrict__ xin,
                                               const float* __restrict__ linW,
                                               const float* __restrict__ linb,
                                               float* __restrict__ out) {
    __shared__ float sW[HID * NC];
    __shared__ float sb[NC];
    for (int i = threadIdx.x; i < HID * NC; i += 128) sW[i] = linW[i];
    if (threadIdx.x < NC) sb[threadIdx.x] = linb[threadIdx.x];
    __syncthreads();
    int t = blockIdx.x * 128 + threadIdx.x;
    if (t >= NPICK) return;
    float lg[NC];
    #pragma unroll
    for (int j = 0; j < NC; j++) lg[j] = sb[j];
    const float4* xr = (const float4*)&xin[(size_t)t * HID];
    #pragma unroll
    for (int k4 = 0; k4 < 16; k4++) {
        float4 v = xr[k4];
        float xs[4] = {v.x, v.y, v.z, v.w};
        #pragma unroll
        for (int q = 0; q < 4; q++) {
            #pragma unroll
            for (int j = 0; j < NC; j++) lg[j] += xs[q] * sW[(k4 * 4 + q) * NC + j];
        }
    }
    float m = lg[0];
    #pragma unroll
    for (int j = 1; j < NC; j++) m = fmaxf(m, lg[j]);
    float ex[NC], s = 0.f;
    #pragma unroll
    for (int j = 0; j < NC; j++) { ex[j] = __expf(lg[j] - m); s += ex[j]; }
    float inv = 1.f / s;
    #pragma unroll
    for (int j = 0; j < NC; j++) out[(size_t)t * NC + j] = ex[j] * inv;
}

// ---------------- launch ----------------
extern "C" void kernel_launch(void* const* d_in, const int* in_sizes, int n_in,
                              void* d_out, int out_size) {
    const float* x      = (const float*)d_in[0];
    const float* eattr  = (const float*)d_in[1];
    const float* encW1  = (const float*)d_in[2];
    const float* encb1  = (const float*)d_in[3];
    const float* encW2  = (const float*)d_in[4];
    const float* encb2  = (const float*)d_in[5];
    const float* convW  = (const float*)d_in[6];
    const float* convB  = (const float*)d_in[7];
    const float* mlpW1  = (const float*)d_in[8];
    const float* mlpb1  = (const float*)d_in[9];
    const float* mlpW2  = (const float*)d_in[10];
    const float* mlpb2  = (const float*)d_in[11];
    const float* linW   = (const float*)d_in[12];
    const float* linb   = (const float*)d_in[13];
    const int* eidx     = (const int*)d_in[14];   // int32 (JAX x64 disabled)
    const int* pick     = (const int*)d_in[15];
    float* out = (float*)d_out;

    const int* rowp = eidx;
    const int* colp = eidx + NE;

    float *xa, *xb, *deg;
    cudaGetSymbolAddress((void**)&xa, g_xa);
    cudaGetSymbolAddress((void**)&xb, g_xb);
    cudaGetSymbolAddress((void**)&deg, g_deg);

    const int EB = (NE + 255) / 256;        // 3125
    const int WB = (NN * 32 + 255) / 256;   // 6250
    const int PB = (NPICK * 32) / 256;      // 512

    // launch index 0..2
    k_fold<<<1, 256>>>(encW1, encb1, encW2, encb2, mlpW1, mlpb1);
    k_zero<<<(4 * NN + 255) / 256, 256>>>();
    k_count<<<EB, 256>>>(colp);

    // launch index 3: k_edge (lands in the ncu -s window)
    k_edge<<<EBLK, 256>>>(eattr, colp, mlpW2, mlpb2);

    // CSR scan + scatter
    k_scan1<<<NSCB, 256>>>();
    k_scan2<<<1, 256>>>();
    k_scan3<<<NSCB, 256>>>();
    k_scatter<<<EB, 256>>>(rowp, colp);

    const float* xin = x;
    float* bufs[2] = { xa, xb };
    for (int l = 0; l < 3; l++) {
        k_gemm<<<WB, 256>>>(xin, convW + l * HID * HID, deg + l * NN);
        k_spmm<<<WB, 256>>>(deg + l * NN, convB + l * HID, bufs[l & 1], l, 1,
                            (const int*)nullptr, NN);
        xin = bufs[l & 1];
    }
    // layer 3: only picked rows, compacted output into xb
    k_gemm<<<WB, 256>>>(xin, convW + 3 * HID * HID, deg + 3 * NN);
    k_spmm<<<PB, 256>>>(deg + 3 * NN, convB + 3 * HID, xb, 3, 0, pick, NPICK);

    k_final<<<32, 128>>>(xb, linW, linb, out);
}